// round 16
// baseline (speedup 1.0000x reference)
#include <cuda_runtime.h>
#include <math.h>

#define N_B      8192
#define N_DEV    100000
#define CONT     62
#define EMB      16
#define FEAT     94
#define FPAD     96
#define KNB      64
#define NH       4
#define NOUT     16
#define HO       64
#define NTHREADS 256
#define FSTR     100   // sFeat row stride in floats
#define NB4      4     // batch elements per CTA
#define MSTR     100   // sM per-head stride

// dynamic smem layout (floats)
#define OFF_FEAT  0          // 2 * 6400
#define OFF_WD2   12800      // 384
#define OFF_M     13184      // 1600
#define OFF_FUS   14784      // 1024
#define OFF_SCR   15808      // 768
#define OFF_E     16576      // 256
#define OFF_NID   16832      // 256 ints
#define SMEM_FLOATS 17088    // 68352 bytes

// ---------------- scratch (written per launch, before gat_kernel) ---------------
__device__ float g_dev_feats[N_DEV * FPAD];  // dense padded device features
__device__ float g_wd2[NH * FPAD];           // Wd[h] @ a2[h]
__device__ float g_vch[NH * FPAD];           // Wc[h] @ a1[h]
__device__ float g_ech[NH];                  // bc·a1 + ab + bd·a2
__device__ float g_Wdp[FPAD * HO];           // Wd as [f][h*16+o], zero rows f>=94
__device__ float g_Wfus[256 * 64];           // padded 256x64: [comb96; dev96; HO64]
__device__ float g_b2f[64];                  // b2 + b1@W2c

// ---- dense device-feature table: warp per row, 8 rows per 256-thread block ----
__global__ __launch_bounds__(NTHREADS) void devfeat_kernel(
    const float* __restrict__ device_cont,
    const int*   __restrict__ device_cat,
    const float* __restrict__ de0,
    const float* __restrict__ de1)
{
    const int lane = threadIdx.x & 31;
    const int warp = threadIdx.x >> 5;
    const int row  = blockIdx.x * 8 + warp;
    if (row >= N_DEV) return;

    float* dst = g_dev_feats + (size_t)row * FPAD;

    if (lane < 31) {
        float2 v = *reinterpret_cast<const float2*>(device_cont + (size_t)row * CONT + 2 * lane);
        *reinterpret_cast<float2*>(dst + 2 * lane) = v;
    } else {
        *reinterpret_cast<float2*>(dst + 94) = make_float2(0.f, 0.f);
    }
    if (lane < 8) {
        int n0 = device_cat[2 * row];
        float2 v = *reinterpret_cast<const float2*>(de0 + (size_t)n0 * EMB + 2 * lane);
        *reinterpret_cast<float2*>(dst + 62 + 2 * lane) = v;
    } else if (lane < 16) {
        int n1 = device_cat[2 * row + 1];
        float2 v = *reinterpret_cast<const float2*>(de1 + (size_t)n1 * EMB + 2 * (lane - 8));
        *reinterpret_cast<float2*>(dst + 78 + 2 * (lane - 8)) = v;
    }
}

__global__ __launch_bounds__(NTHREADS) void prep_kernel(
    const float* __restrict__ Wc, const float* __restrict__ bc,
    const float* __restrict__ Wd, const float* __restrict__ bd,
    const float* __restrict__ aW, const float* __restrict__ ab,
    const float* __restrict__ W1, const float* __restrict__ b1,
    const float* __restrict__ W2, const float* __restrict__ b2)
{
    const int tid = threadIdx.x;

    for (int idx = tid; idx < NH * FPAD; idx += NTHREADS) {
        int h = idx / FPAD, f = idx % FPAD;
        float s2 = 0.f, s1 = 0.f;
        if (f < FEAT) {
            #pragma unroll
            for (int o = 0; o < NOUT; o++) {
                s2 += Wd[(h * FEAT + f) * NOUT + o] * aW[h * 2 * NOUT + NOUT + o];
                s1 += Wc[(h * FEAT + f) * NOUT + o] * aW[h * 2 * NOUT + o];
            }
        }
        g_wd2[idx] = s2;
        g_vch[idx] = s1;
    }
    if (tid < NH) {
        float s = ab[tid];
        #pragma unroll
        for (int o = 0; o < NOUT; o++) {
            s += bc[tid * NOUT + o] * aW[tid * 2 * NOUT + o];
            s += bd[tid * NOUT + o] * aW[tid * 2 * NOUT + NOUT + o];
        }
        g_ech[tid] = s;
    }
    for (int idx = tid; idx < FPAD * HO; idx += NTHREADS) {
        int f = idx >> 6, ho = idx & 63;
        g_Wdp[idx] = (f < FEAT) ? Wd[((ho >> 4) * FEAT + f) * NOUT + (ho & 15)] : 0.f;
    }
    for (int idx = tid; idx < 256 * 64; idx += NTHREADS) {
        int r = idx >> 6, j = idx & 63;
        float v = 0.f;
        if (r < FEAT) {
            v = W2[r * 64 + j];
        } else if (r >= 96 && r < 96 + FEAT) {
            v = W2[(r - 96 + FEAT) * 64 + j];
        } else if (r >= 192) {
            int i = r - 192;
            float s = 0.f;
            #pragma unroll
            for (int t = 0; t < NOUT; t++)
                s += W1[i * NOUT + t] * W2[(2 * FEAT + t) * 64 + j];
            v = s;
        }
        g_Wfus[idx] = v;
    }
    if (tid < 64) {
        float s = b2[tid];
        #pragma unroll
        for (int t = 0; t < NOUT; t++)
            s += b1[t] * W2[(2 * FEAT + t) * 64 + tid];
        g_b2f[tid] = s;
    }
}

// ---------------- main fused kernel: 4 elements/CTA, pipelined gather -----------
__global__ __launch_bounds__(NTHREADS) void gat_kernel(
    const float* __restrict__ combin_cont,
    const int*   __restrict__ combin_cat,
    const int*   __restrict__ combin_idx,
    const int*   __restrict__ device_idx,
    const int*   __restrict__ neighbor_idx,
    const float* __restrict__ ce0,
    const float* __restrict__ ce1,
    const float* __restrict__ bd,
    const float* __restrict__ W3,
    const float* __restrict__ b3,
    const float* __restrict__ W4,
    const float* __restrict__ b4,
    float* __restrict__ out)
{
    extern __shared__ float sm[];
    float* sFeat = sm + OFF_FEAT;     // double buffer [2][6400]
    float* sWd2  = sm + OFF_WD2;
    float* sM    = sm + OFF_M;        // [e][h][MSTR]
    float* sFus  = sm + OFF_FUS;      // [e][comb96|dev96|HO64]
    float* sScr  = sm + OFF_SCR;      // sMp (loop) / sX2+sP2 (post)
    float* sE    = sm + OFF_E;        // attn [h][k]
    int*   sNid  = reinterpret_cast<int*>(sm + OFF_NID);

    float4* sMp = reinterpret_cast<float4*>(sScr);
    float*  sX2 = sScr;
    float*  sP2 = sScr + 256;
    float4* sP3 = reinterpret_cast<float4*>(sFeat);          // post-loop alias
    float4* sP4 = reinterpret_cast<float4*>(sFeat + 1024);

    const int b0   = blockIdx.x * NB4;
    const int tid  = threadIdx.x;
    const int lane = tid & 31;
    const int warp = tid >> 5;

    // ---- Prologue: indices + fusion features for all 4 elements ----
    if (tid < 96) {
        reinterpret_cast<float4*>(sWd2)[tid] = reinterpret_cast<const float4*>(g_wd2)[tid];
    }
    sNid[tid] = neighbor_idx[b0 * KNB + tid];
    #pragma unroll
    for (int pass = 0; pass < 3; pass++) {
        int idx = pass * NTHREADS + tid;        // 0..767
        int e = idx / 192, s = idx - e * 192;
        int b = b0 + e;
        float v = 0.f;
        if (s < 96) {
            int f = s;
            if (f < FEAT) {
                int ci = combin_idx[b];
                if (f < CONT)            v = combin_cont[ci * CONT + f];
                else if (f < CONT + EMB) v = ce0[combin_cat[2 * ci]     * EMB + (f - CONT)];
                else                     v = ce1[combin_cat[2 * ci + 1] * EMB + (f - CONT - EMB)];
            }
        } else {
            int f = s - 96;
            int di = device_idx[b];
            v = g_dev_feats[(size_t)di * FPAD + f];
        }
        sFus[e * 256 + s] = v;
    }
    __syncthreads();

    // ---- Pre-gather element 0 into buffer 0 (all 8 warps) ----
    for (int k = warp; k < KNB; k += 8) {
        const int nid = sNid[k];
        if (lane < 24) {
            float4 v = *reinterpret_cast<const float4*>(g_dev_feats + (size_t)nid * FPAD + 4 * lane);
            *reinterpret_cast<float4*>(sFeat + k * FSTR + 4 * lane) = v;
        }
    }
    __syncthreads();

    // ================= pipelined attention loop =================
    #pragma unroll 1
    for (int ei = 0; ei < NB4; ei++) {
        float* cur = sFeat + (ei & 1) * (KNB * FSTR);
        float* nxt = sFeat + ((ei + 1) & 1) * (KNB * FSTR);

        // ---- parallel phase: warps 0-3 S1+softmax(ei) || warps 4-7 gather(ei+1) ----
        if (warp < 4) {
            const int h = warp;
            // e_base inline (butterfly reduce)
            float eb = 0.f;
            for (int f = lane; f < FEAT; f += 32)
                eb += sFus[ei * 256 + f] * g_vch[h * FPAD + f];
            #pragma unroll
            for (int off = 16; off; off >>= 1) eb += __shfl_xor_sync(0xffffffffu, eb, off);
            eb += g_ech[h];

            // two 94-dots per lane: k=lane, k=lane+32
            const float4* fp0 = reinterpret_cast<const float4*>(cur + lane * FSTR);
            const float4* fp1 = reinterpret_cast<const float4*>(cur + (lane + 32) * FSTR);
            const float4* wp  = reinterpret_cast<const float4*>(sWd2 + h * FPAD);
            float a0 = 0.f, a1 = 0.f, a2 = 0.f, a3 = 0.f;
            float c0 = 0.f, c1 = 0.f, c2 = 0.f, c3 = 0.f;
            #pragma unroll
            for (int i = 0; i < FPAD / 4; i++) {
                float4 w = wp[i];
                float4 x = fp0[i];
                float4 y = fp1[i];
                a0 += x.x * w.x; a1 += x.y * w.y; a2 += x.z * w.z; a3 += x.w * w.w;
                c0 += y.x * w.x; c1 += y.y * w.y; c2 += y.z * w.z; c3 += y.w * w.w;
            }
            float v0 = (a0 + a1) + (a2 + a3) + eb;
            float v1 = (c0 + c1) + (c2 + c3) + eb;
            v0 = (v0 >= 0.f) ? v0 : 0.2f * v0;
            v1 = (v1 >= 0.f) ? v1 : 0.2f * v1;

            // warp softmax over 64 values (2 per lane)
            float m = fmaxf(v0, v1);
            #pragma unroll
            for (int off = 16; off; off >>= 1) m = fmaxf(m, __shfl_xor_sync(0xffffffffu, m, off));
            float e0 = __expf(v0 - m), e1 = __expf(v1 - m);
            float s = e0 + e1;
            #pragma unroll
            for (int off = 16; off; off >>= 1) s += __shfl_xor_sync(0xffffffffu, s, off);
            float inv = __frcp_rn(s);
            sE[h * KNB + lane]      = e0 * inv;
            sE[h * KNB + lane + 32] = e1 * inv;
        } else if (ei < NB4 - 1) {
            // gather element ei+1 into the other buffer (4 warps x 16 rows)
            for (int k = warp - 4; k < KNB; k += 4) {
                const int nid = sNid[(ei + 1) * KNB + k];
                if (lane < 24) {
                    float4 v = *reinterpret_cast<const float4*>(g_dev_feats + (size_t)nid * FPAD + 4 * lane);
                    *reinterpret_cast<float4*>(nxt + k * FSTR + 4 * lane) = v;
                }
            }
        }
        __syncthreads();

        // ---- S2 partial: thread (kc, h, f4): float4 over 32-k half ----
        if (tid < 192) {
            int kc = tid / 96;
            int r  = tid - kc * 96;
            int h  = r / 24, f4 = r - h * 24;
            const float4* fp4 = reinterpret_cast<const float4*>(cur) + f4;
            const float*  ep  = sE + h * KNB + kc * 32;
            float4 acc = make_float4(0.f, 0.f, 0.f, 0.f);
            #pragma unroll 8
            for (int i = 0; i < 32; i++) {
                float ev = ep[i];
                float4 a = fp4[(kc * 32 + i) * (FSTR / 4)];
                acc.x += ev * a.x; acc.y += ev * a.y; acc.z += ev * a.z; acc.w += ev * a.w;
            }
            sMp[tid] = acc;
        }
        __syncthreads();

        // ---- S2 combine: sM[e][h][f4] = p(kc=0) + p(kc=1) ----
        if (tid < 96) {
            int h = tid / 24, f4 = tid - h * 24;
            float4 a = sMp[tid], b = sMp[96 + tid];
            float4 r = make_float4(a.x + b.x, a.y + b.y, a.z + b.z, a.w + b.w);
            *reinterpret_cast<float4*>(sM + ei * (NH * MSTR) + h * MSTR + 4 * f4) = r;
        }
        __syncthreads();
    }

    // ---- S3 partial: thread (e, fc, ho4): 24 f x 4 ho, float4 weights ----
    {
        int e = tid >> 6, fc = (tid >> 4) & 3, ho4 = tid & 15;
        int h = ho4 >> 2;
        const float* mp = sM + e * (NH * MSTR) + h * MSTR + fc * 24;
        const float4* wdp = reinterpret_cast<const float4*>(g_Wdp);
        float4 acc = make_float4(0.f, 0.f, 0.f, 0.f);
        #pragma unroll 4
        for (int i = 0; i < 24; i++) {
            int f = fc * 24 + i;
            float m = mp[i];
            float4 w = wdp[f * 16 + ho4];
            acc.x += m * w.x; acc.y += m * w.y; acc.z += m * w.z; acc.w += m * w.w;
        }
        sP3[(e * 16 + ho4) * 4 + fc] = acc;
    }
    __syncthreads();

    // ---- S3 combine: head_out -> sFus[e][192..255] (elu) ----
    if (tid < 64) {
        int e = tid >> 4, ho4 = tid & 15;
        float4 a = sP3[(e * 16 + ho4) * 4 + 0];
        float4 b = sP3[(e * 16 + ho4) * 4 + 1];
        float4 c = sP3[(e * 16 + ho4) * 4 + 2];
        float4 d = sP3[(e * 16 + ho4) * 4 + 3];
        float4 bdv = reinterpret_cast<const float4*>(bd)[ho4];
        float r0 = a.x + b.x + c.x + d.x + bdv.x;
        float r1 = a.y + b.y + c.y + d.y + bdv.y;
        float r2 = a.z + b.z + c.z + d.z + bdv.z;
        float r3 = a.w + b.w + c.w + d.w + bdv.w;
        float* dst = sFus + e * 256 + 192 + 4 * ho4;
        dst[0] = (r0 > 0.f) ? r0 : (__expf(r0) - 1.f);
        dst[1] = (r1 > 0.f) ? r1 : (__expf(r1) - 1.f);
        dst[2] = (r2 > 0.f) ? r2 : (__expf(r2) - 1.f);
        dst[3] = (r3 > 0.f) ? r3 : (__expf(r3) - 1.f);
    }
    __syncthreads();

    // ---- S4 partial: thread (e, rc, j4): 64 rows x 4 j, float4 weights ----
    {
        int e = tid >> 6, rc = (tid >> 4) & 3, j4 = tid & 15;
        const float* fp = sFus + e * 256 + rc * 64;
        const float4* wf = reinterpret_cast<const float4*>(g_Wfus) + rc * 64 * 16 + j4;
        float4 acc = make_float4(0.f, 0.f, 0.f, 0.f);
        #pragma unroll 4
        for (int i = 0; i < 64; i++) {
            float fv = fp[i];
            float4 w = wf[i * 16];
            acc.x += fv * w.x; acc.y += fv * w.y; acc.z += fv * w.z; acc.w += fv * w.w;
        }
        sP4[(e * 16 + j4) * 4 + rc] = acc;
    }
    __syncthreads();

    // ---- S4 combine: x2 = relu(b2f + sum of rc partials) ----
    if (tid < 64) {
        int e = tid >> 4, j4 = tid & 15;
        float4 a = sP4[(e * 16 + j4) * 4 + 0];
        float4 b = sP4[(e * 16 + j4) * 4 + 1];
        float4 c = sP4[(e * 16 + j4) * 4 + 2];
        float4 d = sP4[(e * 16 + j4) * 4 + 3];
        float4 bb = reinterpret_cast<const float4*>(g_b2f)[j4];
        float* dst = sX2 + e * 64 + 4 * j4;
        dst[0] = fmaxf(a.x + b.x + c.x + d.x + bb.x, 0.f);
        dst[1] = fmaxf(a.y + b.y + c.y + d.y + bb.y, 0.f);
        dst[2] = fmaxf(a.z + b.z + c.z + d.z + bb.z, 0.f);
        dst[3] = fmaxf(a.w + b.w + c.w + d.w + bb.w, 0.f);
    }
    __syncthreads();

    // ---- S5 partial: x3[e][j] over k-halves ----
    {
        int e = tid >> 6, c = (tid >> 5) & 1, j = lane;
        float s = 0.f;
        #pragma unroll
        for (int k = c * 32; k < c * 32 + 32; k++)
            s += sX2[e * 64 + k] * W3[k * 32 + j];
        sP2[tid] = s;
    }
    __syncthreads();

    // ---- final: combine halves, W4 dot, sigmoid, write 4 outputs ----
    if (tid < 128) {
        int e = tid >> 5, j = lane;
        float x3 = b3[j] + sP2[e * 64 + j] + sP2[e * 64 + 32 + j];
        x3 = fmaxf(x3, 0.f);
        float v = x3 * W4[j];
        #pragma unroll
        for (int off = 16; off; off >>= 1) v += __shfl_xor_sync(0xffffffffu, v, off);
        if (j == 0) out[b0 + e] = 1.f / (1.f + __expf(-(v + b4[0])));
    }
}

extern "C" void kernel_launch(void* const* d_in, const int* in_sizes, int n_in,
                              void* d_out, int out_size)
{
    (void)in_sizes; (void)n_in; (void)out_size;

    devfeat_kernel<<<(N_DEV + 7) / 8, NTHREADS>>>(
        (const float*)d_in[2],   // device_cont
        (const int*)  d_in[3],   // device_cat
        (const float*)d_in[9],   // de0
        (const float*)d_in[10]); // de1

    prep_kernel<<<1, NTHREADS>>>(
        (const float*)d_in[11],  // Wc
        (const float*)d_in[12],  // bc
        (const float*)d_in[13],  // Wd
        (const float*)d_in[14],  // bd
        (const float*)d_in[15],  // aW
        (const float*)d_in[16],  // ab
        (const float*)d_in[17],  // W1
        (const float*)d_in[18],  // b1
        (const float*)d_in[19],  // W2
        (const float*)d_in[20]); // b2

    const int smem_bytes = SMEM_FLOATS * 4;   // 68352
    cudaFuncSetAttribute(gat_kernel, cudaFuncAttributeMaxDynamicSharedMemorySize, smem_bytes);
    gat_kernel<<<N_B / NB4, NTHREADS, smem_bytes>>>(
        (const float*)d_in[0],   // combin_cont
        (const int*)  d_in[1],   // combin_cat
        (const int*)  d_in[4],   // combin_idx
        (const int*)  d_in[5],   // device_idx
        (const int*)  d_in[6],   // neighbor_idx
        (const float*)d_in[7],   // ce0
        (const float*)d_in[8],   // ce1
        (const float*)d_in[14],  // bd
        (const float*)d_in[21],  // W3
        (const float*)d_in[22],  // b3
        (const float*)d_in[23],  // W4
        (const float*)d_in[24],  // b4
        (float*)d_out);
}